// round 6
// baseline (speedup 1.0000x reference)
#include <cuda_runtime.h>
#include <cuda_bf16.h>
#include <cstdint>

#define B_    4
#define C_    256
#define H_    80
#define W_    80
#define HW    6400
#define K2    9
#define KDIM  2304
#define COUT  256
#define NCHUNK 72          // 9 taps * 8 channel-groups of 32

// ---------------- device scratch ----------------
__device__ float    g_xnhwc[B_ * HW * C_];        // x in NHWC
__device__ float    g_owT[KDIM * 20];             // offset weights transposed (18->20 pad)
__device__ uint32_t g_wA2[NCHUNK * 2 * 256 * 16]; // bf16x2 words [q][term][row][kw]
__device__ float4   g_twgt[B_ * K2 * HW];         // bilinear weights * validity
__device__ int4     g_tidx[B_ * K2 * HW];         // clamped NHWC bases

// ---------------- mma helpers ----------------
__device__ __forceinline__ void mma16816(float* d, const uint32_t* a, const uint32_t* b) {
    asm volatile(
        "mma.sync.aligned.m16n8k16.row.col.f32.bf16.bf16.f32 "
        "{%0,%1,%2,%3}, {%4,%5,%6,%7}, {%8,%9}, {%0,%1,%2,%3};"
        : "+f"(d[0]), "+f"(d[1]), "+f"(d[2]), "+f"(d[3])
        : "r"(a[0]), "r"(a[1]), "r"(a[2]), "r"(a[3]), "r"(b[0]), "r"(b[1]));
}

__device__ __forceinline__ void ldsm4(uint32_t* r, uint32_t addr) {
    asm volatile("ldmatrix.sync.aligned.m8n8.x4.shared.b16 {%0,%1,%2,%3}, [%4];"
                 : "=r"(r[0]), "=r"(r[1]), "=r"(r[2]), "=r"(r[3]) : "r"(addr));
}

__device__ __forceinline__ uint32_t pack_bf16(float lo_v, float hi_v) {
    __nv_bfloat162 h;
    h.x = __float2bfloat16(lo_v);
    h.y = __float2bfloat16(hi_v);
    return *(uint32_t*)&h;
}

// ---------------- kernel 1: NCHW -> NHWC transpose -------------------------
__global__ void k_transpose(const float* __restrict__ x) {
    __shared__ float tile[32][33];
    int b   = blockIdx.z;
    int hw0 = blockIdx.x * 32;
    int c0  = blockIdx.y * 32;
    int tx = threadIdx.x, ty = threadIdx.y;
    const float* xb = x + b * C_ * HW;
    #pragma unroll
    for (int i = 0; i < 32; i += 8)
        tile[ty + i][tx] = xb[(c0 + ty + i) * HW + hw0 + tx];
    __syncthreads();
    float* ob = g_xnhwc + b * HW * C_;
    #pragma unroll
    for (int i = 0; i < 32; i += 8)
        ob[(hw0 + ty + i) * C_ + c0 + tx] = tile[tx][ty + i];
}

// ---------------- kernel 2: merged prep (owT transpose + conv-w split) -----
// blocks [0,180): offset-weight transpose; blocks [180,2484): bf16 hi/lo split
// of conv weights into plain [q][term][row][kw] bf16x2 words.
#define OWT_BLOCKS 180
__global__ void k_prep(const float* __restrict__ ow, const float* __restrict__ cw) {
    int blk = blockIdx.x;
    if (blk < OWT_BLOCKS) {
        int idx = blk * 256 + threadIdx.x;
        if (idx < KDIM * 20) {
            int row = idx / 20, oc = idx % 20;
            g_owT[idx] = (oc < 18) ? __ldg(ow + oc * KDIM + row) : 0.f;
        }
    } else {
        int e = (blk - OWT_BLOCKS) * 256 + threadIdx.x;  // < 72*2*256*16
        if (e < NCHUNK * 2 * 256 * 16) {
            int kw   = e & 15;
            int row  = (e >> 4) & 255;
            int term = (e >> 12) & 1;
            int q    = e >> 13;
            int tap  = q >> 3;
            int c0   = (q & 7) * 32 + kw * 2;
            float w0 = __ldg(cw + row * KDIM + c0 * 9 + tap);
            float w1 = __ldg(cw + row * KDIM + (c0 + 1) * 9 + tap);
            if (term) {
                w0 -= __bfloat162float(__float2bfloat16(w0));
                w1 -= __bfloat162float(__float2bfloat16(w1));
            }
            g_wA2[e] = pack_bf16(w0, w1);
        }
    }
}

// ---------------- kernel 3: offset conv + tap metadata ---------------------
__global__ void __launch_bounds__(256) k_offset(const float* __restrict__ x,
                                                const float* __restrict__ off_b) {
    __shared__ float red[8][32][18];
    __shared__ float offs[32][18];

    int pg   = blockIdx.x;                 // 0..799
    int b    = pg / (HW / 32);
    int hw0  = (pg % (HW / 32)) * 32;
    int lane = threadIdx.x & 31;
    int wq   = threadIdx.x >> 5;
    int p    = hw0 + lane;
    int py   = p / W_, px = p % W_;

    int noff[9];
    #pragma unroll
    for (int nb = 0; nb < 9; nb++) {
        int ny = py + nb / 3 - 1, nx = px + nb % 3 - 1;
        noff[nb] = (ny >= 0 && ny < H_ && nx >= 0 && nx < W_) ? ny * W_ + nx : -1;
    }

    float acc[18];
    #pragma unroll
    for (int i = 0; i < 18; i++) acc[i] = 0.f;

    int c0 = wq * 32;
    const float* xb = x + (size_t)(b * C_ + c0) * HW;
    for (int c = 0; c < 32; c++) {
        const float* xc = xb + c * HW;
        const float4* wr = (const float4*)(g_owT + (size_t)(c0 + c) * 180);
        #pragma unroll
        for (int nb = 0; nb < 9; nb++) {
            float xv = (noff[nb] >= 0) ? __ldg(xc + noff[nb]) : 0.f;
            const float4* w = wr + nb * 5;
            float wv[20];
            *(float4*)&wv[0]  = __ldg(w + 0);
            *(float4*)&wv[4]  = __ldg(w + 1);
            *(float4*)&wv[8]  = __ldg(w + 2);
            *(float4*)&wv[12] = __ldg(w + 3);
            *(float4*)&wv[16] = __ldg(w + 4);
            #pragma unroll
            for (int i = 0; i < 18; i++) acc[i] = fmaf(xv, wv[i], acc[i]);
        }
    }

    #pragma unroll
    for (int i = 0; i < 18; i++) red[wq][lane][i] = acc[i];
    __syncthreads();

    for (int u = threadIdx.x; u < 32 * 18; u += 256) {
        int l = u / 18, oc = u % 18;
        float s = 0.f;
        #pragma unroll
        for (int qx = 0; qx < 8; qx++) s += red[qx][l][oc];
        offs[l][oc] = s + __ldg(off_b + oc);
    }
    __syncthreads();

    for (int u = threadIdx.x; u < 32 * 9; u += 256) {
        int l = u / 9, k = u % 9;
        float dy = offs[l][2 * k], dx = offs[l][2 * k + 1];
        int pp = hw0 + l;
        int yy = pp / W_, xx = pp % W_;
        float fy = (float)(yy + k / 3 - 1) + dy;
        float fx = (float)(xx + k % 3 - 1) + dx;
        float y0f = floorf(fy), x0f = floorf(fx);
        float wy = fy - y0f, wx = fx - x0f;
        int y0 = (int)y0f, x0 = (int)x0f;
        int y1 = y0 + 1,   x1 = x0 + 1;
        float vy0 = (y0 >= 0 && y0 < H_) ? 1.f : 0.f;
        float vy1 = (y1 >= 0 && y1 < H_) ? 1.f : 0.f;
        float vx0 = (x0 >= 0 && x0 < W_) ? 1.f : 0.f;
        float vx1 = (x1 >= 0 && x1 < W_) ? 1.f : 0.f;
        int cy0 = min(max(y0, 0), H_ - 1), cy1 = min(max(y1, 0), H_ - 1);
        int cx0 = min(max(x0, 0), W_ - 1), cx1 = min(max(x1, 0), W_ - 1);
        float4 wt;
        wt.x = (1.f - wy) * (1.f - wx) * vy0 * vx0;
        wt.y = (1.f - wy) * wx         * vy0 * vx1;
        wt.z = wy * (1.f - wx)         * vy1 * vx0;
        wt.w = wy * wx                 * vy1 * vx1;
        int4 id;
        id.x = (cy0 * W_ + cx0) * C_;
        id.y = (cy0 * W_ + cx1) * C_;
        id.z = (cy1 * W_ + cx0) * C_;
        id.w = (cy1 * W_ + cx1) * C_;
        int m = (b * 9 + k) * HW + pp;
        g_twgt[m] = wt;
        g_tidx[m] = id;
    }
}

// ---------------- kernel 4: main GEMM via mma.sync bf16 split --------------
// Block: 128 M x 128 N, 256 threads (8 warps = 2 Mwarp x 4 Nwarp, warp tile
// 64x32). A staged once per chunk into SMEM (coalesced) and read via
// conflict-free ldmatrix (80 B row stride); B gathered+split into SMEM.
#define BROW 20    // u32 words per row (80 B stride, 16 used)

__global__ void __launch_bounds__(256, 2) k_main(const float* __restrict__ cb,
                                                 float* __restrict__ out) {
    __shared__ uint32_t sA[2][128 * BROW];   // [term][row*20 + kw]
    __shared__ uint32_t sB[2][128 * BROW];   // [term][pixel*20 + word]

    int tid  = threadIdx.x;
    int wid  = tid >> 5, lane = tid & 31;
    int mb   = blockIdx.x & 1;
    int nblk = blockIdx.x >> 1;              // 0..199 (4 batches x 50 tiles)
    int b    = nblk / (HW / 128);
    int hw0  = (nblk % (HW / 128)) * 128;
    int wm   = wid >> 2, wn = wid & 3;

    float acc[4][4][4];
    #pragma unroll
    for (int i = 0; i < 4; i++)
        #pragma unroll
        for (int j = 0; j < 4; j++)
            #pragma unroll
            for (int r = 0; r < 4; r++) acc[i][j][r] = 0.f;

    const float4* xb4 = (const float4*)(g_xnhwc + (size_t)b * HW * C_);
    int b9 = b * 9;
    int p = tid >> 1, half = tid & 1;

    uint32_t sa0 = (uint32_t)__cvta_generic_to_shared(&sA[0][0]);
    uint32_t sb0 = (uint32_t)__cvta_generic_to_shared(&sB[0][0]);
    uint32_t sb1 = (uint32_t)__cvta_generic_to_shared(&sB[1][0]);

    // B ldmatrix lane address (within a term plane)
    int mat = lane >> 3, mrow = lane & 7;
    int jd  = mat >> 1, kh = mat & 1;
    uint32_t lmB = ((wn * 32 + jd * 8 + mrow) * BROW + kh * 4) * 4;
    // A ldmatrix lane address components
    int arow  = ((lane >> 3) & 1) * 8 + (lane & 7);
    int acolw = (lane >> 4) * 4;
    uint32_t lmA = (uint32_t)(arow * BROW + acolw) * 4;

    const uint4* gA4 = (const uint4*)g_wA2;

    for (int q = 0; q < NCHUNK; q++) {
        int tap = q >> 3, cg = q & 7;
        int mm = (b9 + tap) * HW + hw0 + p;
        float4 wt = g_twgt[mm];
        int4  id  = g_tidx[mm];

        __syncthreads();   // previous chunk's mma done -> safe to overwrite

        // ---- stage A chunk (this CTA's 128 rows, both terms) ----
        {
            int srcbase = q * 2048 + mb * 512;   // uint4 units; term stride 1024
            #pragma unroll
            for (int i = 0; i < 4; i++) {
                int u    = i * 256 + tid;        // 0..1023
                int term = u >> 9;
                int r    = (u >> 2) & 127;
                int kw4  = u & 3;
                uint4 v = __ldg(gA4 + srcbase + term * 1024 + r * 4 + kw4);
                *(uint4*)&sA[term][r * BROW + kw4 * 4] = v;
            }
        }

        // ---- gather B: bilinear, split hi/lo ----
        #pragma unroll
        for (int qq = 0; qq < 4; qq++) {
            int c = cg * 32 + half * 16 + qq * 4;
            float4 t0 = __ldg(xb4 + ((id.x + c) >> 2));
            float4 t1 = __ldg(xb4 + ((id.y + c) >> 2));
            float4 t2 = __ldg(xb4 + ((id.z + c) >> 2));
            float4 t3 = __ldg(xb4 + ((id.w + c) >> 2));
            float4 v;
            v.x = wt.x * t0.x + wt.y * t1.x + wt.z * t2.x + wt.w * t3.x;
            v.y = wt.x * t0.y + wt.y * t1.y + wt.z * t2.y + wt.w * t3.y;
            v.z = wt.x * t0.z + wt.y * t1.z + wt.z * t2.z + wt.w * t3.z;
            v.w = wt.x * t0.w + wt.y * t1.w + wt.z * t2.w + wt.w * t3.w;
            uint32_t h01 = pack_bf16(v.x, v.y);
            uint32_t h23 = pack_bf16(v.z, v.w);
            __nv_bfloat162 hh01 = *(__nv_bfloat162*)&h01;
            __nv_bfloat162 hh23 = *(__nv_bfloat162*)&h23;
            float lx = v.x - __bfloat162float(hh01.x);
            float ly = v.y - __bfloat162float(hh01.y);
            float lz = v.z - __bfloat162float(hh23.x);
            float lw = v.w - __bfloat162float(hh23.y);
            uint32_t l01 = pack_bf16(lx, ly);
            uint32_t l23 = pack_bf16(lz, lw);
            int word = p * BROW + half * 8 + qq * 2;
            *(uint2*)&sB[0][word] = make_uint2(h01, h23);
            *(uint2*)&sB[1][word] = make_uint2(l01, l23);
        }
        __syncthreads();

        // ---- mma phase ----
        #pragma unroll
        for (int s = 0; s < 2; s++) {
            uint32_t soff = (uint32_t)(s * 32);              // s*8 words
            uint32_t Bh[8], Bl[8];
            ldsm4(Bh + 0, sb0 + lmB + soff);
            ldsm4(Bh + 4, sb0 + lmB + soff + (uint32_t)(16 * BROW * 4));
            ldsm4(Bl + 0, sb1 + lmB + soff);
            ldsm4(Bl + 4, sb1 + lmB + soff + (uint32_t)(16 * BROW * 4));
            uint32_t Ah[4][4];
            #pragma unroll
            for (int i = 0; i < 4; i++)
                ldsm4(Ah[i], sa0 + lmA + soff + (uint32_t)((wm * 64 + i * 16) * BROW * 4));
            #pragma unroll
            for (int i = 0; i < 4; i++)
                #pragma unroll
                for (int j = 0; j < 4; j++)
                    mma16816(acc[i][j], Ah[i], Bh + 2 * j);
            #pragma unroll
            for (int i = 0; i < 4; i++)
                #pragma unroll
                for (int j = 0; j < 4; j++)
                    mma16816(acc[i][j], Ah[i], Bl + 2 * j);
            #pragma unroll
            for (int i = 0; i < 4; i++) {
                uint32_t Al[4];
                ldsm4(Al, sa0 + (uint32_t)(128 * BROW * 4) + lmA + soff +
                          (uint32_t)((wm * 64 + i * 16) * BROW * 4));
                #pragma unroll
                for (int j = 0; j < 4; j++)
                    mma16816(acc[i][j], Al, Bh + 2 * j);
            }
        }
    }

    // ---- epilogue: bias + NCHW store ----
    int q_ = lane >> 2, t = lane & 3;
    #pragma unroll
    for (int i = 0; i < 4; i++) {
        int o0 = mb * 128 + wm * 64 + i * 16 + q_;
        float bias0 = __ldg(cb + o0);
        float bias1 = __ldg(cb + o0 + 8);
        float* r0 = out + (size_t)(b * COUT + o0) * HW + hw0 + wn * 32;
        float* r1 = out + (size_t)(b * COUT + o0 + 8) * HW + hw0 + wn * 32;
        #pragma unroll
        for (int j = 0; j < 4; j++) {
            float2 s0, s1;
            s0.x = acc[i][j][0] + bias0; s0.y = acc[i][j][1] + bias0;
            s1.x = acc[i][j][2] + bias1; s1.y = acc[i][j][3] + bias1;
            *(float2*)(r0 + j * 8 + t * 2) = s0;
            *(float2*)(r1 + j * 8 + t * 2) = s1;
        }
    }
}

// ---------------- launch -----------------------------------------------------
extern "C" void kernel_launch(void* const* d_in, const int* in_sizes, int n_in,
                              void* d_out, int out_size) {
    const float* x  = (const float*)d_in[0];
    const float* ow = (const float*)d_in[1];
    const float* ob = (const float*)d_in[2];
    const float* cw = (const float*)d_in[3];
    const float* cb = (const float*)d_in[4];
    float* out      = (float*)d_out;

    {
        dim3 grid(HW / 32, C_ / 32, B_);
        dim3 block(32, 8);
        k_transpose<<<grid, block>>>(x);
    }
    k_prep<<<OWT_BLOCKS + (NCHUNK * 2 * 256 * 16) / 256, 256>>>(ow, cw);
    k_offset<<<B_ * HW / 32, 256>>>(x, ob);
    k_main<<<2 * B_ * (HW / 128), 256>>>(cb, out);
}

// round 7
// speedup vs baseline: 1.3084x; 1.3084x over previous
#include <cuda_runtime.h>
#include <cuda_bf16.h>
#include <cstdint>

#define B_    4
#define C_    256
#define H_    80
#define W_    80
#define HW    6400
#define K2    9
#define KDIM  2304
#define COUT  256
#define NCHUNK 72          // 9 taps * 8 channel-groups of 32

// ---------------- device scratch ----------------
__device__ float    g_xnhwc[B_ * HW * C_];        // x in NHWC
__device__ float    g_owT[KDIM * 20];             // offset weights transposed (18->20 pad)
__device__ uint32_t g_wA2[NCHUNK * 2 * 256 * 16]; // bf16x2 words [q][term][row][kw]
__device__ float4   g_twgt[B_ * K2 * HW];         // bilinear weights * validity
__device__ int4     g_tidx[B_ * K2 * HW];         // clamped NHWC bases

// ---------------- mma helpers ----------------
__device__ __forceinline__ void mma16816(float* d, const uint32_t* a, const uint32_t* b) {
    asm volatile(
        "mma.sync.aligned.m16n8k16.row.col.f32.bf16.bf16.f32 "
        "{%0,%1,%2,%3}, {%4,%5,%6,%7}, {%8,%9}, {%0,%1,%2,%3};"
        : "+f"(d[0]), "+f"(d[1]), "+f"(d[2]), "+f"(d[3])
        : "r"(a[0]), "r"(a[1]), "r"(a[2]), "r"(a[3]), "r"(b[0]), "r"(b[1]));
}

__device__ __forceinline__ void ldsm4(uint32_t* r, uint32_t addr) {
    asm volatile("ldmatrix.sync.aligned.m8n8.x4.shared.b16 {%0,%1,%2,%3}, [%4];"
                 : "=r"(r[0]), "=r"(r[1]), "=r"(r[2]), "=r"(r[3]) : "r"(addr));
}

__device__ __forceinline__ uint32_t pack_bf16(float lo_v, float hi_v) {
    __nv_bfloat162 h;
    h.x = __float2bfloat16(lo_v);
    h.y = __float2bfloat16(hi_v);
    return *(uint32_t*)&h;
}

// ---------------- kernel 1: NCHW -> NHWC transpose -------------------------
__global__ void k_transpose(const float* __restrict__ x) {
    __shared__ float tile[32][33];
    int b   = blockIdx.z;
    int hw0 = blockIdx.x * 32;
    int c0  = blockIdx.y * 32;
    int tx = threadIdx.x, ty = threadIdx.y;
    const float* xb = x + b * C_ * HW;
    #pragma unroll
    for (int i = 0; i < 32; i += 8)
        tile[ty + i][tx] = xb[(c0 + ty + i) * HW + hw0 + tx];
    __syncthreads();
    float* ob = g_xnhwc + b * HW * C_;
    #pragma unroll
    for (int i = 0; i < 32; i += 8)
        ob[(hw0 + ty + i) * C_ + c0 + tx] = tile[tx][ty + i];
}

// ---------------- kernel 2: merged prep (owT transpose + conv-w split) -----
#define OWT_BLOCKS 180
__global__ void k_prep(const float* __restrict__ ow, const float* __restrict__ cw) {
    int blk = blockIdx.x;
    if (blk < OWT_BLOCKS) {
        int idx = blk * 256 + threadIdx.x;
        if (idx < KDIM * 20) {
            int row = idx / 20, oc = idx % 20;
            g_owT[idx] = (oc < 18) ? __ldg(ow + oc * KDIM + row) : 0.f;
        }
    } else {
        int e = (blk - OWT_BLOCKS) * 256 + threadIdx.x;  // < 72*2*256*16
        if (e < NCHUNK * 2 * 256 * 16) {
            int kw   = e & 15;
            int row  = (e >> 4) & 255;
            int term = (e >> 12) & 1;
            int q    = e >> 13;
            int tap  = q >> 3;
            int c0   = (q & 7) * 32 + kw * 2;
            float w0 = __ldg(cw + row * KDIM + c0 * 9 + tap);
            float w1 = __ldg(cw + row * KDIM + (c0 + 1) * 9 + tap);
            if (term) {
                w0 -= __bfloat162float(__float2bfloat16(w0));
                w1 -= __bfloat162float(__float2bfloat16(w1));
            }
            g_wA2[e] = pack_bf16(w0, w1);
        }
    }
}

// ---------------- kernel 3: offset conv + tap metadata ---------------------
__global__ void __launch_bounds__(256) k_offset(const float* __restrict__ x,
                                                const float* __restrict__ off_b) {
    __shared__ float red[8][32][18];
    __shared__ float offs[32][18];

    int pg   = blockIdx.x;                 // 0..799
    int b    = pg / (HW / 32);
    int hw0  = (pg % (HW / 32)) * 32;
    int lane = threadIdx.x & 31;
    int wq   = threadIdx.x >> 5;
    int p    = hw0 + lane;
    int py   = p / W_, px = p % W_;

    int noff[9];
    #pragma unroll
    for (int nb = 0; nb < 9; nb++) {
        int ny = py + nb / 3 - 1, nx = px + nb % 3 - 1;
        noff[nb] = (ny >= 0 && ny < H_ && nx >= 0 && nx < W_) ? ny * W_ + nx : -1;
    }

    float acc[18];
    #pragma unroll
    for (int i = 0; i < 18; i++) acc[i] = 0.f;

    int c0 = wq * 32;
    const float* xb = x + (size_t)(b * C_ + c0) * HW;
    for (int c = 0; c < 32; c++) {
        const float* xc = xb + c * HW;
        const float4* wr = (const float4*)(g_owT + (size_t)(c0 + c) * 180);
        #pragma unroll
        for (int nb = 0; nb < 9; nb++) {
            float xv = (noff[nb] >= 0) ? __ldg(xc + noff[nb]) : 0.f;
            const float4* w = wr + nb * 5;
            float wv[20];
            *(float4*)&wv[0]  = __ldg(w + 0);
            *(float4*)&wv[4]  = __ldg(w + 1);
            *(float4*)&wv[8]  = __ldg(w + 2);
            *(float4*)&wv[12] = __ldg(w + 3);
            *(float4*)&wv[16] = __ldg(w + 4);
            #pragma unroll
            for (int i = 0; i < 18; i++) acc[i] = fmaf(xv, wv[i], acc[i]);
        }
    }

    #pragma unroll
    for (int i = 0; i < 18; i++) red[wq][lane][i] = acc[i];
    __syncthreads();

    for (int u = threadIdx.x; u < 32 * 18; u += 256) {
        int l = u / 18, oc = u % 18;
        float s = 0.f;
        #pragma unroll
        for (int qx = 0; qx < 8; qx++) s += red[qx][l][oc];
        offs[l][oc] = s + __ldg(off_b + oc);
    }
    __syncthreads();

    for (int u = threadIdx.x; u < 32 * 9; u += 256) {
        int l = u / 9, k = u % 9;
        float dy = offs[l][2 * k], dx = offs[l][2 * k + 1];
        int pp = hw0 + l;
        int yy = pp / W_, xx = pp % W_;
        float fy = (float)(yy + k / 3 - 1) + dy;
        float fx = (float)(xx + k % 3 - 1) + dx;
        float y0f = floorf(fy), x0f = floorf(fx);
        float wy = fy - y0f, wx = fx - x0f;
        int y0 = (int)y0f, x0 = (int)x0f;
        int y1 = y0 + 1,   x1 = x0 + 1;
        float vy0 = (y0 >= 0 && y0 < H_) ? 1.f : 0.f;
        float vy1 = (y1 >= 0 && y1 < H_) ? 1.f : 0.f;
        float vx0 = (x0 >= 0 && x0 < W_) ? 1.f : 0.f;
        float vx1 = (x1 >= 0 && x1 < W_) ? 1.f : 0.f;
        int cy0 = min(max(y0, 0), H_ - 1), cy1 = min(max(y1, 0), H_ - 1);
        int cx0 = min(max(x0, 0), W_ - 1), cx1 = min(max(x1, 0), W_ - 1);
        float4 wt;
        wt.x = (1.f - wy) * (1.f - wx) * vy0 * vx0;
        wt.y = (1.f - wy) * wx         * vy0 * vx1;
        wt.z = wy * (1.f - wx)         * vy1 * vx0;
        wt.w = wy * wx                 * vy1 * vx1;
        int4 id;
        id.x = (cy0 * W_ + cx0) * C_;
        id.y = (cy0 * W_ + cx1) * C_;
        id.z = (cy1 * W_ + cx0) * C_;
        id.w = (cy1 * W_ + cx1) * C_;
        int m = (b * 9 + k) * HW + pp;
        g_twgt[m] = wt;
        g_tidx[m] = id;
    }
}

// ---------------- kernel 4: main GEMM via mma.sync bf16 split --------------
// 128M x 128N tile, 256 threads. Gather is channel-major: warp = 4 pixels x
// 8 channel-lanes -> each tap LDG.128 touches exactly 4 aligned 128B lines.
#define BROW 20    // u32 words per row (80 B stride, 16 used)

__global__ void __launch_bounds__(256, 2) k_main(const float* __restrict__ cb,
                                                 float* __restrict__ out) {
    __shared__ uint32_t sA[2][128 * BROW];   // [term][row*20 + kw]
    __shared__ uint32_t sB[2][128 * BROW];   // [term][pixel*20 + word]

    int tid  = threadIdx.x;
    int wid  = tid >> 5, lane = tid & 31;
    int mb   = blockIdx.x & 1;
    int nblk = blockIdx.x >> 1;              // 0..199 (4 batches x 50 tiles)
    int b    = nblk / (HW / 128);
    int hw0  = (nblk % (HW / 128)) * 128;
    int wm   = wid >> 2, wn = wid & 3;

    float acc[4][4][4];
    #pragma unroll
    for (int i = 0; i < 4; i++)
        #pragma unroll
        for (int j = 0; j < 4; j++)
            #pragma unroll
            for (int r = 0; r < 4; r++) acc[i][j][r] = 0.f;

    const float4* xb4 = (const float4*)(g_xnhwc + (size_t)b * HW * C_);
    int b9 = b * 9;
    int px8 = tid >> 3;        // pixel group 0..31
    int l8  = tid & 7;         // channel lane 0..7

    uint32_t sa0 = (uint32_t)__cvta_generic_to_shared(&sA[0][0]);
    uint32_t sb0 = (uint32_t)__cvta_generic_to_shared(&sB[0][0]);
    uint32_t sb1 = (uint32_t)__cvta_generic_to_shared(&sB[1][0]);

    // B ldmatrix lane address (within a term plane)
    int mat = lane >> 3, mrow = lane & 7;
    int jd  = mat >> 1, kh = mat & 1;
    uint32_t lmB = ((wn * 32 + jd * 8 + mrow) * BROW + kh * 4) * 4;
    // A ldmatrix lane address components
    int arow  = ((lane >> 3) & 1) * 8 + (lane & 7);
    int acolw = (lane >> 4) * 4;
    uint32_t lmA = (uint32_t)(arow * BROW + acolw) * 4;

    const uint4* gA4 = (const uint4*)g_wA2;

    for (int q = 0; q < NCHUNK; q++) {
        int tap = q >> 3, cg = q & 7;
        int mmb = (b9 + tap) * HW + hw0;
        int cc  = cg * 32 + l8 * 4;          // channel base for this lane

        __syncthreads();   // previous chunk's mma done -> safe to overwrite

        // ---- stage A chunk (this CTA's 128 rows, both terms) ----
        {
            int srcbase = q * 2048 + mb * 512;   // uint4 units; term stride 1024
            #pragma unroll
            for (int i = 0; i < 4; i++) {
                int u    = i * 256 + tid;        // 0..1023
                int term = u >> 9;
                int r    = (u >> 2) & 127;
                int kw4  = u & 3;
                uint4 v = __ldg(gA4 + srcbase + term * 1024 + r * 4 + kw4);
                *(uint4*)&sA[term][r * BROW + kw4 * 4] = v;
            }
        }

        // ---- gather B (channel-major): 4 passes x 4 taps ----
        #pragma unroll
        for (int pass = 0; pass < 4; pass++) {
            int pp = px8 + pass * 32;            // pixel 0..127
            int mm = mmb + pp;
            float4 wt = g_twgt[mm];              // 8-lane broadcast
            int4   id = g_tidx[mm];
            float4 t0 = __ldg(xb4 + ((id.x + cc) >> 2));
            float4 t1 = __ldg(xb4 + ((id.y + cc) >> 2));
            float4 t2 = __ldg(xb4 + ((id.z + cc) >> 2));
            float4 t3 = __ldg(xb4 + ((id.w + cc) >> 2));
            float4 v;
            v.x = wt.x * t0.x + wt.y * t1.x + wt.z * t2.x + wt.w * t3.x;
            v.y = wt.x * t0.y + wt.y * t1.y + wt.z * t2.y + wt.w * t3.y;
            v.z = wt.x * t0.z + wt.y * t1.z + wt.z * t2.z + wt.w * t3.z;
            v.w = wt.x * t0.w + wt.y * t1.w + wt.z * t2.w + wt.w * t3.w;
            uint32_t h01 = pack_bf16(v.x, v.y);
            uint32_t h23 = pack_bf16(v.z, v.w);
            __nv_bfloat162 hh01 = *(__nv_bfloat162*)&h01;
            __nv_bfloat162 hh23 = *(__nv_bfloat162*)&h23;
            float lx = v.x - __bfloat162float(hh01.x);
            float ly = v.y - __bfloat162float(hh01.y);
            float lz = v.z - __bfloat162float(hh23.x);
            float lw = v.w - __bfloat162float(hh23.y);
            uint32_t l01 = pack_bf16(lx, ly);
            uint32_t l23 = pack_bf16(lz, lw);
            int word = pp * BROW + l8 * 2;
            *(uint2*)&sB[0][word] = make_uint2(h01, h23);
            *(uint2*)&sB[1][word] = make_uint2(l01, l23);
        }
        __syncthreads();

        // ---- mma phase ----
        #pragma unroll
        for (int s = 0; s < 2; s++) {
            uint32_t soff = (uint32_t)(s * 32);              // s*8 words
            uint32_t Bh[8], Bl[8];
            ldsm4(Bh + 0, sb0 + lmB + soff);
            ldsm4(Bh + 4, sb0 + lmB + soff + (uint32_t)(16 * BROW * 4));
            ldsm4(Bl + 0, sb1 + lmB + soff);
            ldsm4(Bl + 4, sb1 + lmB + soff + (uint32_t)(16 * BROW * 4));
            uint32_t Ah[4][4];
            #pragma unroll
            for (int i = 0; i < 4; i++)
                ldsm4(Ah[i], sa0 + lmA + soff + (uint32_t)((wm * 64 + i * 16) * BROW * 4));
            #pragma unroll
            for (int i = 0; i < 4; i++)
                #pragma unroll
                for (int j = 0; j < 4; j++)
                    mma16816(acc[i][j], Ah[i], Bh + 2 * j);
            #pragma unroll
            for (int i = 0; i < 4; i++)
                #pragma unroll
                for (int j = 0; j < 4; j++)
                    mma16816(acc[i][j], Ah[i], Bl + 2 * j);
            #pragma unroll
            for (int i = 0; i < 4; i++) {
                uint32_t Al[4];
                ldsm4(Al, sa0 + (uint32_t)(128 * BROW * 4) + lmA + soff +
                          (uint32_t)((wm * 64 + i * 16) * BROW * 4));
                #pragma unroll
                for (int j = 0; j < 4; j++)
                    mma16816(acc[i][j], Al, Bh + 2 * j);
            }
        }
    }

    // ---- epilogue: bias + NCHW store ----
    int q_ = lane >> 2, t = lane & 3;
    #pragma unroll
    for (int i = 0; i < 4; i++) {
        int o0 = mb * 128 + wm * 64 + i * 16 + q_;
        float bias0 = __ldg(cb + o0);
        float bias1 = __ldg(cb + o0 + 8);
        float* r0 = out + (size_t)(b * COUT + o0) * HW + hw0 + wn * 32;
        float* r1 = out + (size_t)(b * COUT + o0 + 8) * HW + hw0 + wn * 32;
        #pragma unroll
        for (int j = 0; j < 4; j++) {
            float2 s0, s1;
            s0.x = acc[i][j][0] + bias0; s0.y = acc[i][j][1] + bias0;
            s1.x = acc[i][j][2] + bias1; s1.y = acc[i][j][3] + bias1;
            *(float2*)(r0 + j * 8 + t * 2) = s0;
            *(float2*)(r1 + j * 8 + t * 2) = s1;
        }
    }
}

// ---------------- launch -----------------------------------------------------
extern "C" void kernel_launch(void* const* d_in, const int* in_sizes, int n_in,
                              void* d_out, int out_size) {
    const float* x  = (const float*)d_in[0];
    const float* ow = (const float*)d_in[1];
    const float* ob = (const float*)d_in[2];
    const float* cw = (const float*)d_in[3];
    const float* cb = (const float*)d_in[4];
    float* out      = (float*)d_out;

    {
        dim3 grid(HW / 32, C_ / 32, B_);
        dim3 block(32, 8);
        k_transpose<<<grid, block>>>(x);
    }
    k_prep<<<OWT_BLOCKS + (NCHUNK * 2 * 256 * 16) / 256, 256>>>(ow, cw);
    k_offset<<<B_ * HW / 32, 256>>>(x, ob);
    k_main<<<2 * B_ * (HW / 128), 256>>>(cb, out);
}

// round 8
// speedup vs baseline: 1.5780x; 1.2061x over previous
#include <cuda_runtime.h>
#include <cuda_bf16.h>
#include <cstdint>

#define B_    4
#define C_    256
#define H_    80
#define W_    80
#define HW    6400
#define K2    9
#define KDIM  2304
#define COUT  256
#define NCHUNK 72          // 9 taps * 8 channel-groups of 32
#define BROW  20           // u32 words per row (80 B stride, 16 used)

// ---------------- device scratch ----------------
__device__ float    g_xnhwc[B_ * HW * C_];        // x in NHWC
__device__ float    g_owT[KDIM * 20];             // offset weights transposed (18->20 pad)
__device__ uint32_t g_wA2[NCHUNK * 2 * 256 * 16]; // bf16x2 words [q][term][row][kw]
__device__ float4   g_twgt[B_ * K2 * HW];         // bilinear weights * validity
__device__ int4     g_tidx[B_ * K2 * HW];         // clamped NHWC bases

// ---------------- mma helpers ----------------
__device__ __forceinline__ void mma16816(float* d, const uint32_t* a, const uint32_t* b) {
    asm volatile(
        "mma.sync.aligned.m16n8k16.row.col.f32.bf16.bf16.f32 "
        "{%0,%1,%2,%3}, {%4,%5,%6,%7}, {%8,%9}, {%0,%1,%2,%3};"
        : "+f"(d[0]), "+f"(d[1]), "+f"(d[2]), "+f"(d[3])
        : "r"(a[0]), "r"(a[1]), "r"(a[2]), "r"(a[3]), "r"(b[0]), "r"(b[1]));
}

__device__ __forceinline__ void ldsm4(uint32_t* r, uint32_t addr) {
    asm volatile("ldmatrix.sync.aligned.m8n8.x4.shared.b16 {%0,%1,%2,%3}, [%4];"
                 : "=r"(r[0]), "=r"(r[1]), "=r"(r[2]), "=r"(r[3]) : "r"(addr));
}

__device__ __forceinline__ uint32_t pack_bf16(float lo_v, float hi_v) {
    __nv_bfloat162 h;
    h.x = __float2bfloat16(lo_v);
    h.y = __float2bfloat16(hi_v);
    return *(uint32_t*)&h;
}

// ---------------- kernel 1: NCHW -> NHWC transpose -------------------------
__global__ void k_transpose(const float* __restrict__ x) {
    __shared__ float tile[32][33];
    int b   = blockIdx.z;
    int hw0 = blockIdx.x * 32;
    int c0  = blockIdx.y * 32;
    int tx = threadIdx.x, ty = threadIdx.y;
    const float* xb = x + b * C_ * HW;
    #pragma unroll
    for (int i = 0; i < 32; i += 8)
        tile[ty + i][tx] = xb[(c0 + ty + i) * HW + hw0 + tx];
    __syncthreads();
    float* ob = g_xnhwc + b * HW * C_;
    #pragma unroll
    for (int i = 0; i < 32; i += 8)
        ob[(hw0 + ty + i) * C_ + c0 + tx] = tile[tx][ty + i];
}

// ---------------- kernel 2: merged prep (owT transpose + conv-w split) -----
#define OWT_BLOCKS 180
__global__ void k_prep(const float* __restrict__ ow, const float* __restrict__ cw) {
    int blk = blockIdx.x;
    if (blk < OWT_BLOCKS) {
        int idx = blk * 256 + threadIdx.x;
        if (idx < KDIM * 20) {
            int row = idx / 20, oc = idx % 20;
            g_owT[idx] = (oc < 18) ? __ldg(ow + oc * KDIM + row) : 0.f;
        }
    } else {
        int e = (blk - OWT_BLOCKS) * 256 + threadIdx.x;
        if (e < NCHUNK * 2 * 256 * 16) {
            int kw   = e & 15;
            int row  = (e >> 4) & 255;
            int term = (e >> 12) & 1;
            int q    = e >> 13;
            int tap  = q >> 3;
            int c0   = (q & 7) * 32 + kw * 2;
            float w0 = __ldg(cw + row * KDIM + c0 * 9 + tap);
            float w1 = __ldg(cw + row * KDIM + (c0 + 1) * 9 + tap);
            if (term) {
                w0 -= __bfloat162float(__float2bfloat16(w0));
                w1 -= __bfloat162float(__float2bfloat16(w1));
            }
            g_wA2[e] = pack_bf16(w0, w1);
        }
    }
}

// ---------------- kernel 3: offset conv + tap metadata ---------------------
__global__ void __launch_bounds__(256) k_offset(const float* __restrict__ x,
                                                const float* __restrict__ off_b) {
    __shared__ float red[8][32][18];
    __shared__ float offs[32][18];

    int pg   = blockIdx.x;                 // 0..799
    int b    = pg / (HW / 32);
    int hw0  = (pg % (HW / 32)) * 32;
    int lane = threadIdx.x & 31;
    int wq   = threadIdx.x >> 5;
    int p    = hw0 + lane;
    int py   = p / W_, px = p % W_;

    int noff[9];
    #pragma unroll
    for (int nb = 0; nb < 9; nb++) {
        int ny = py + nb / 3 - 1, nx = px + nb % 3 - 1;
        noff[nb] = (ny >= 0 && ny < H_ && nx >= 0 && nx < W_) ? ny * W_ + nx : -1;
    }

    float acc[18];
    #pragma unroll
    for (int i = 0; i < 18; i++) acc[i] = 0.f;

    int c0 = wq * 32;
    const float* xb = x + (size_t)(b * C_ + c0) * HW;
    for (int c = 0; c < 32; c++) {
        const float* xc = xb + c * HW;
        const float4* wr = (const float4*)(g_owT + (size_t)(c0 + c) * 180);
        #pragma unroll
        for (int nb = 0; nb < 9; nb++) {
            float xv = (noff[nb] >= 0) ? __ldg(xc + noff[nb]) : 0.f;
            const float4* w = wr + nb * 5;
            float wv[20];
            *(float4*)&wv[0]  = __ldg(w + 0);
            *(float4*)&wv[4]  = __ldg(w + 1);
            *(float4*)&wv[8]  = __ldg(w + 2);
            *(float4*)&wv[12] = __ldg(w + 3);
            *(float4*)&wv[16] = __ldg(w + 4);
            #pragma unroll
            for (int i = 0; i < 18; i++) acc[i] = fmaf(xv, wv[i], acc[i]);
        }
    }

    #pragma unroll
    for (int i = 0; i < 18; i++) red[wq][lane][i] = acc[i];
    __syncthreads();

    for (int u = threadIdx.x; u < 32 * 18; u += 256) {
        int l = u / 18, oc = u % 18;
        float s = 0.f;
        #pragma unroll
        for (int qx = 0; qx < 8; qx++) s += red[qx][l][oc];
        offs[l][oc] = s + __ldg(off_b + oc);
    }
    __syncthreads();

    for (int u = threadIdx.x; u < 32 * 9; u += 256) {
        int l = u / 9, k = u % 9;
        float dy = offs[l][2 * k], dx = offs[l][2 * k + 1];
        int pp = hw0 + l;
        int yy = pp / W_, xx = pp % W_;
        float fy = (float)(yy + k / 3 - 1) + dy;
        float fx = (float)(xx + k % 3 - 1) + dx;
        float y0f = floorf(fy), x0f = floorf(fx);
        float wy = fy - y0f, wx = fx - x0f;
        int y0 = (int)y0f, x0 = (int)x0f;
        int y1 = y0 + 1,   x1 = x0 + 1;
        float vy0 = (y0 >= 0 && y0 < H_) ? 1.f : 0.f;
        float vy1 = (y1 >= 0 && y1 < H_) ? 1.f : 0.f;
        float vx0 = (x0 >= 0 && x0 < W_) ? 1.f : 0.f;
        float vx1 = (x1 >= 0 && x1 < W_) ? 1.f : 0.f;
        int cy0 = min(max(y0, 0), H_ - 1), cy1 = min(max(y1, 0), H_ - 1);
        int cx0 = min(max(x0, 0), W_ - 1), cx1 = min(max(x1, 0), W_ - 1);
        float4 wt;
        wt.x = (1.f - wy) * (1.f - wx) * vy0 * vx0;
        wt.y = (1.f - wy) * wx         * vy0 * vx1;
        wt.z = wy * (1.f - wx)         * vy1 * vx0;
        wt.w = wy * wx                 * vy1 * vx1;
        int4 id;
        id.x = (cy0 * W_ + cx0) * C_;
        id.y = (cy0 * W_ + cx1) * C_;
        id.z = (cy1 * W_ + cx0) * C_;
        id.w = (cy1 * W_ + cx1) * C_;
        int m = (b * 9 + k) * HW + pp;
        g_twgt[m] = wt;
        g_tidx[m] = id;
    }
}

// ---------------- kernel 4: warp-specialized main GEMM ---------------------
// CTA = 384 threads: warps 0-7 = mma (M=256 x N=64; warp tile 64x32),
// warps 8-11 = producers (gather chunk q+1 + stage A(q+1)) into double-
// buffered SMEM. One __syncthreads per chunk; overlap by construction.
// Dynamic smem (words): sA[buf][term][256*BROW] at 0 (buf*10240+term*5120),
// sB[buf][term][64*BROW] at 20480 (buf*2560+term*1280). Total 100 KB.
#define SA_WORDS 20480
#define SMEM_WORDS (SA_WORDS + 5120)

__global__ void __launch_bounds__(384, 1) k_main(const float* __restrict__ cb,
                                                 float* __restrict__ out) {
    extern __shared__ uint32_t smw[];

    int tid  = threadIdx.x;
    int wid  = tid >> 5, lane = tid & 31;
    int blk  = blockIdx.x;                   // 0..399
    int b    = blk / (HW / 64);
    int hw0  = (blk % (HW / 64)) * 64;
    int b9   = b * 9;

    const float4* xb4 = (const float4*)(g_xnhwc + (size_t)b * HW * C_);
    const uint4*  gA4 = (const uint4*)g_wA2;

    uint32_t smem_u = (uint32_t)__cvta_generic_to_shared(smw);

    if (wid >= 8) {
        // ================= producer warps =================
        int gtid = tid - 256;                // 0..127
        int gl8  = gtid & 7;
        int gpx  = gtid >> 3;                // 0..15
        for (int nq = 0; nq < NCHUNK; nq++) {
            int nbuf = nq & 1;
            // ---- stage A chunk nq (32 KB, coalesced, linear) ----
            {
                const uint4* src = gA4 + nq * 2048;
                #pragma unroll
                for (int i = 0; i < 16; i++) {
                    int u = i * 128 + gtid;            // 0..2047
                    uint4 v = __ldg(src + u);
                    int term = u >> 10, r = (u >> 2) & 255, kw4 = u & 3;
                    *(uint4*)&smw[nbuf * 10240 + term * 5120 + r * BROW + kw4 * 4] = v;
                }
            }
            // ---- gather chunk nq: 64 px, 32 ch (channel-major lanes) ----
            int tap = nq >> 3, cg = nq & 7;
            int cc  = cg * 32 + gl8 * 4;
            int mmb = (b9 + tap) * HW + hw0;
            #pragma unroll
            for (int pass = 0; pass < 4; pass++) {
                int pp = gpx + pass * 16;
                int mm = mmb + pp;
                float4 wt = g_twgt[mm];
                int4   id = g_tidx[mm];
                float4 t0 = __ldg(xb4 + ((id.x + cc) >> 2));
                float4 t1 = __ldg(xb4 + ((id.y + cc) >> 2));
                float4 t2 = __ldg(xb4 + ((id.z + cc) >> 2));
                float4 t3 = __ldg(xb4 + ((id.w + cc) >> 2));
                float4 v;
                v.x = wt.x * t0.x + wt.y * t1.x + wt.z * t2.x + wt.w * t3.x;
                v.y = wt.x * t0.y + wt.y * t1.y + wt.z * t2.y + wt.w * t3.y;
                v.z = wt.x * t0.z + wt.y * t1.z + wt.z * t2.z + wt.w * t3.z;
                v.w = wt.x * t0.w + wt.y * t1.w + wt.z * t2.w + wt.w * t3.w;
                uint32_t h01 = pack_bf16(v.x, v.y);
                uint32_t h23 = pack_bf16(v.z, v.w);
                __nv_bfloat162 hh01 = *(__nv_bfloat162*)&h01;
                __nv_bfloat162 hh23 = *(__nv_bfloat162*)&h23;
                float lx = v.x - __bfloat162float(hh01.x);
                float ly = v.y - __bfloat162float(hh01.y);
                float lz = v.z - __bfloat162float(hh23.x);
                float lw = v.w - __bfloat162float(hh23.y);
                int word = pp * BROW + gl8 * 2;
                *(uint2*)&smw[SA_WORDS + nbuf * 2560 + word] = make_uint2(h01, h23);
                *(uint2*)&smw[SA_WORDS + nbuf * 2560 + 1280 + word] =
                    make_uint2(pack_bf16(lx, ly), pack_bf16(lz, lw));
            }
            __syncthreads();   // chunk nq ready; mma warps may consume
        }
        // mma warps do one final iteration on the last chunk
        __syncthreads();
    } else {
        // ================= mma warps =================
        int wm = wid >> 1, wn = wid & 1;

        float acc[4][4][4];
        #pragma unroll
        for (int i = 0; i < 4; i++)
            #pragma unroll
            for (int j = 0; j < 4; j++)
                #pragma unroll
                for (int r = 0; r < 4; r++) acc[i][j][r] = 0.f;

        // B ldmatrix lane address (within a term plane)
        int mat = lane >> 3, mrow = lane & 7;
        int jd  = mat >> 1, kh = mat & 1;
        uint32_t lmB = ((wn * 32 + jd * 8 + mrow) * BROW + kh * 4) * 4;
        // A ldmatrix lane address
        int arow  = ((lane >> 3) & 1) * 8 + (lane & 7);
        int acolw = (lane >> 4) * 4;
        uint32_t lmA = (uint32_t)(arow * BROW + acolw) * 4;

        for (int q = 0; q < NCHUNK; q++) {
            __syncthreads();   // wait for chunk q to be produced
            int buf = q & 1;
            uint32_t aH = smem_u + (uint32_t)(buf * 10240) * 4;
            uint32_t aL = aH + (uint32_t)(5120 * 4);
            uint32_t bH = smem_u + (uint32_t)((SA_WORDS + buf * 2560) * 4);
            uint32_t bL = bH + (uint32_t)(1280 * 4);

            #pragma unroll
            for (int s = 0; s < 2; s++) {
                uint32_t soff = (uint32_t)(s * 32);
                uint32_t Bh[8], Bl[8];
                ldsm4(Bh + 0, bH + lmB + soff);
                ldsm4(Bh + 4, bH + lmB + soff + (uint32_t)(16 * BROW * 4));
                ldsm4(Bl + 0, bL + lmB + soff);
                ldsm4(Bl + 4, bL + lmB + soff + (uint32_t)(16 * BROW * 4));
                uint32_t Ah[4][4];
                #pragma unroll
                for (int i = 0; i < 4; i++)
                    ldsm4(Ah[i], aH + lmA + soff + (uint32_t)((wm * 64 + i * 16) * BROW * 4));
                #pragma unroll
                for (int i = 0; i < 4; i++)
                    #pragma unroll
                    for (int j = 0; j < 4; j++)
                        mma16816(acc[i][j], Ah[i], Bh + 2 * j);
                #pragma unroll
                for (int i = 0; i < 4; i++)
                    #pragma unroll
                    for (int j = 0; j < 4; j++)
                        mma16816(acc[i][j], Ah[i], Bl + 2 * j);
                #pragma unroll
                for (int i = 0; i < 4; i++) {
                    uint32_t Al[4];
                    ldsm4(Al, aL + lmA + soff + (uint32_t)((wm * 64 + i * 16) * BROW * 4));
                    #pragma unroll
                    for (int j = 0; j < 4; j++)
                        mma16816(acc[i][j], Al, Bh + 2 * j);
                }
            }
        }

        // ---- epilogue: bias + NCHW store ----
        int q_ = lane >> 2, t = lane & 3;
        #pragma unroll
        for (int i = 0; i < 4; i++) {
            int o0 = wm * 64 + i * 16 + q_;
            float bias0 = __ldg(cb + o0);
            float bias1 = __ldg(cb + o0 + 8);
            float* r0 = out + (size_t)(b * COUT + o0) * HW + hw0 + wn * 32;
            float* r1 = out + (size_t)(b * COUT + o0 + 8) * HW + hw0 + wn * 32;
            #pragma unroll
            for (int j = 0; j < 4; j++) {
                float2 s0, s1;
                s0.x = acc[i][j][0] + bias0; s0.y = acc[i][j][1] + bias0;
                s1.x = acc[i][j][2] + bias1; s1.y = acc[i][j][3] + bias1;
                *(float2*)(r0 + j * 8 + t * 2) = s0;
                *(float2*)(r1 + j * 8 + t * 2) = s1;
            }
        }
    }
}

// ---------------- launch -----------------------------------------------------
extern "C" void kernel_launch(void* const* d_in, const int* in_sizes, int n_in,
                              void* d_out, int out_size) {
    const float* x  = (const float*)d_in[0];
    const float* ow = (const float*)d_in[1];
    const float* ob = (const float*)d_in[2];
    const float* cw = (const float*)d_in[3];
    const float* cb = (const float*)d_in[4];
    float* out      = (float*)d_out;

    cudaFuncSetAttribute(k_main, cudaFuncAttributeMaxDynamicSharedMemorySize,
                         SMEM_WORDS * 4);

    {
        dim3 grid(HW / 32, C_ / 32, B_);
        dim3 block(32, 8);
        k_transpose<<<grid, block>>>(x);
    }
    k_prep<<<OWT_BLOCKS + (NCHUNK * 2 * 256 * 16) / 256, 256>>>(ow, cw);
    k_offset<<<B_ * HW / 32, 256>>>(x, ob);

    // one CTA per (batch, 64-pixel tile): 400 CTAs
    k_main<<<B_ * (HW / 64), 384, SMEM_WORDS * 4>>>(cb, out);
}

// round 9
// speedup vs baseline: 1.7422x; 1.1041x over previous
#include <cuda_runtime.h>
#include <cuda_bf16.h>
#include <cstdint>

#define B_    4
#define C_    256
#define H_    80
#define W_    80
#define HW    6400
#define K2    9
#define KDIM  2304
#define COUT  256
#define NCHUNK 72          // 9 taps * 8 channel-groups of 32
#define BROW  20           // u32 words per row (80 B stride, 16 used)

// ---------------- device scratch ----------------
__device__ float    g_xnhwc[B_ * HW * C_];        // x in NHWC
__device__ float    g_owT[KDIM * 20];             // offset weights transposed (18->20 pad)
__device__ uint4    g_wA[NCHUNK * 2 * 16 * 2 * 32]; // fragment-packed bf16 weights (hi/lo)
__device__ float4   g_twgt[B_ * K2 * HW];         // bilinear weights * validity
__device__ int4     g_tidx[B_ * K2 * HW];         // clamped NHWC bases

// ---------------- mma helpers ----------------
__device__ __forceinline__ void mma16816(float* d, const uint32_t* a, const uint32_t* b) {
    asm volatile(
        "mma.sync.aligned.m16n8k16.row.col.f32.bf16.bf16.f32 "
        "{%0,%1,%2,%3}, {%4,%5,%6,%7}, {%8,%9}, {%0,%1,%2,%3};"
        : "+f"(d[0]), "+f"(d[1]), "+f"(d[2]), "+f"(d[3])
        : "r"(a[0]), "r"(a[1]), "r"(a[2]), "r"(a[3]), "r"(b[0]), "r"(b[1]));
}

__device__ __forceinline__ void ldsm4(uint32_t* r, uint32_t addr) {
    asm volatile("ldmatrix.sync.aligned.m8n8.x4.shared.b16 {%0,%1,%2,%3}, [%4];"
                 : "=r"(r[0]), "=r"(r[1]), "=r"(r[2]), "=r"(r[3]) : "r"(addr));
}

__device__ __forceinline__ uint32_t pack_bf16(float lo_v, float hi_v) {
    __nv_bfloat162 h;
    h.x = __float2bfloat16(lo_v);
    h.y = __float2bfloat16(hi_v);
    return *(uint32_t*)&h;
}

// ---------------- kernel 1: NCHW -> NHWC transpose -------------------------
__global__ void k_transpose(const float* __restrict__ x) {
    __shared__ float tile[32][33];
    int b   = blockIdx.z;
    int hw0 = blockIdx.x * 32;
    int c0  = blockIdx.y * 32;
    int tx = threadIdx.x, ty = threadIdx.y;
    const float* xb = x + b * C_ * HW;
    #pragma unroll
    for (int i = 0; i < 32; i += 8)
        tile[ty + i][tx] = xb[(c0 + ty + i) * HW + hw0 + tx];
    __syncthreads();
    float* ob = g_xnhwc + b * HW * C_;
    #pragma unroll
    for (int i = 0; i < 32; i += 8)
        ob[(hw0 + ty + i) * C_ + c0 + tx] = tile[tx][ty + i];
}

// ---------------- kernel 2: merged prep (owT + fragment-packed conv-w) -----
// g_wA index: ((((q*2 + term)*16 + mt)*2 + s)*32 + lane): uint4 = 4 A-frag regs.
#define OWT_BLOCKS 180
__global__ void k_prep(const float* __restrict__ ow, const float* __restrict__ cw) {
    int blk = blockIdx.x;
    if (blk < OWT_BLOCKS) {
        int idx = blk * 256 + threadIdx.x;
        if (idx < KDIM * 20) {
            int row = idx / 20, oc = idx % 20;
            g_owT[idx] = (oc < 18) ? __ldg(ow + oc * KDIM + row) : 0.f;
        }
    } else {
        int e = (blk - OWT_BLOCKS) * 256 + threadIdx.x;
        if (e < NCHUNK * 2 * 16 * 2 * 32) {
            int lane = e & 31;
            int s    = (e >> 5) & 1;
            int mt   = (e >> 6) & 15;
            int term = (e >> 10) & 1;
            int q    = e >> 11;
            int tap   = q >> 3;
            int cbase = (q & 7) * 32;
            uint32_t r[4];
            #pragma unroll
            for (int rr = 0; rr < 4; rr++) {
                int m  = mt * 16 + (lane >> 2) + ((rr & 1) << 3);
                int kl = s * 16 + (lane & 3) * 2 + ((rr >> 1) << 3);
                float w0 = __ldg(cw + m * KDIM + (cbase + kl) * 9 + tap);
                float w1 = __ldg(cw + m * KDIM + (cbase + kl + 1) * 9 + tap);
                if (term) {
                    w0 -= __bfloat162float(__float2bfloat16(w0));
                    w1 -= __bfloat162float(__float2bfloat16(w1));
                }
                r[rr] = pack_bf16(w0, w1);
            }
            g_wA[e] = make_uint4(r[0], r[1], r[2], r[3]);
        }
    }
}

// ---------------- kernel 3: offset conv + tap metadata ---------------------
__global__ void __launch_bounds__(256) k_offset(const float* __restrict__ x,
                                                const float* __restrict__ off_b) {
    __shared__ float red[8][32][18];
    __shared__ float offs[32][18];

    int pg   = blockIdx.x;                 // 0..799
    int b    = pg / (HW / 32);
    int hw0  = (pg % (HW / 32)) * 32;
    int lane = threadIdx.x & 31;
    int wq   = threadIdx.x >> 5;
    int p    = hw0 + lane;
    int py   = p / W_, px = p % W_;

    int noff[9];
    #pragma unroll
    for (int nb = 0; nb < 9; nb++) {
        int ny = py + nb / 3 - 1, nx = px + nb % 3 - 1;
        noff[nb] = (ny >= 0 && ny < H_ && nx >= 0 && nx < W_) ? ny * W_ + nx : -1;
    }

    float acc[18];
    #pragma unroll
    for (int i = 0; i < 18; i++) acc[i] = 0.f;

    int c0 = wq * 32;
    const float* xb = x + (size_t)(b * C_ + c0) * HW;
    for (int c = 0; c < 32; c++) {
        const float* xc = xb + c * HW;
        const float4* wr = (const float4*)(g_owT + (size_t)(c0 + c) * 180);
        #pragma unroll
        for (int nb = 0; nb < 9; nb++) {
            float xv = (noff[nb] >= 0) ? __ldg(xc + noff[nb]) : 0.f;
            const float4* w = wr + nb * 5;
            float wv[20];
            *(float4*)&wv[0]  = __ldg(w + 0);
            *(float4*)&wv[4]  = __ldg(w + 1);
            *(float4*)&wv[8]  = __ldg(w + 2);
            *(float4*)&wv[12] = __ldg(w + 3);
            *(float4*)&wv[16] = __ldg(w + 4);
            #pragma unroll
            for (int i = 0; i < 18; i++) acc[i] = fmaf(xv, wv[i], acc[i]);
        }
    }

    #pragma unroll
    for (int i = 0; i < 18; i++) red[wq][lane][i] = acc[i];
    __syncthreads();

    for (int u = threadIdx.x; u < 32 * 18; u += 256) {
        int l = u / 18, oc = u % 18;
        float s = 0.f;
        #pragma unroll
        for (int qx = 0; qx < 8; qx++) s += red[qx][l][oc];
        offs[l][oc] = s + __ldg(off_b + oc);
    }
    __syncthreads();

    for (int u = threadIdx.x; u < 32 * 9; u += 256) {
        int l = u / 9, k = u % 9;
        float dy = offs[l][2 * k], dx = offs[l][2 * k + 1];
        int pp = hw0 + l;
        int yy = pp / W_, xx = pp % W_;
        float fy = (float)(yy + k / 3 - 1) + dy;
        float fx = (float)(xx + k % 3 - 1) + dx;
        float y0f = floorf(fy), x0f = floorf(fx);
        float wy = fy - y0f, wx = fx - x0f;
        int y0 = (int)y0f, x0 = (int)x0f;
        int y1 = y0 + 1,   x1 = x0 + 1;
        float vy0 = (y0 >= 0 && y0 < H_) ? 1.f : 0.f;
        float vy1 = (y1 >= 0 && y1 < H_) ? 1.f : 0.f;
        float vx0 = (x0 >= 0 && x0 < W_) ? 1.f : 0.f;
        float vx1 = (x1 >= 0 && x1 < W_) ? 1.f : 0.f;
        int cy0 = min(max(y0, 0), H_ - 1), cy1 = min(max(y1, 0), H_ - 1);
        int cx0 = min(max(x0, 0), W_ - 1), cx1 = min(max(x1, 0), W_ - 1);
        float4 wt;
        wt.x = (1.f - wy) * (1.f - wx) * vy0 * vx0;
        wt.y = (1.f - wy) * wx         * vy0 * vx1;
        wt.z = wy * (1.f - wx)         * vy1 * vx0;
        wt.w = wy * wx                 * vy1 * vx1;
        int4 id;
        id.x = (cy0 * W_ + cx0) * C_;
        id.y = (cy0 * W_ + cx1) * C_;
        id.z = (cy1 * W_ + cx0) * C_;
        id.w = (cy1 * W_ + cx1) * C_;
        int m = (b * 9 + k) * HW + pp;
        g_twgt[m] = wt;
        g_tidx[m] = id;
    }
}

// ---------------- kernel 4: warp-specialized main GEMM ---------------------
// CTA = 384 threads: warps 0-7 = mma (M=256 x N=64; warp tile 64x32),
// warps 8-11 = producers (gather only). A fragments come straight from
// global (fragment-packed, L1-resident). Double-buffered sB (20 KB).
__global__ void __launch_bounds__(384, 1) k_main(const float* __restrict__ cb,
                                                 float* __restrict__ out) {
    __shared__ uint32_t sB[2][2][64 * BROW];   // [buf][term][pixel*20 + word]

    int tid  = threadIdx.x;
    int wid  = tid >> 5, lane = tid & 31;
    int blk  = blockIdx.x;                   // 0..399
    int b    = blk / (HW / 64);
    int hw0  = (blk % (HW / 64)) * 64;
    int b9   = b * 9;

    const float4* xb4 = (const float4*)(g_xnhwc + (size_t)b * HW * C_);

    if (wid >= 8) {
        // ================= producer warps (gather only) =================
        int gtid = tid - 256;                // 0..127
        int gl8  = gtid & 7;
        int gpx  = gtid >> 3;                // 0..15
        for (int nq = 0; nq < NCHUNK; nq++) {
            int nbuf = nq & 1;
            int tap = nq >> 3, cg = nq & 7;
            int cc  = cg * 32 + gl8 * 4;
            int mmb = (b9 + tap) * HW + hw0;
            #pragma unroll
            for (int pass = 0; pass < 4; pass++) {
                int pp = gpx + pass * 16;
                int mm = mmb + pp;
                float4 wt = g_twgt[mm];
                int4   id = g_tidx[mm];
                float4 t0 = __ldg(xb4 + ((id.x + cc) >> 2));
                float4 t1 = __ldg(xb4 + ((id.y + cc) >> 2));
                float4 t2 = __ldg(xb4 + ((id.z + cc) >> 2));
                float4 t3 = __ldg(xb4 + ((id.w + cc) >> 2));
                float4 v;
                v.x = wt.x * t0.x + wt.y * t1.x + wt.z * t2.x + wt.w * t3.x;
                v.y = wt.x * t0.y + wt.y * t1.y + wt.z * t2.y + wt.w * t3.y;
                v.z = wt.x * t0.z + wt.y * t1.z + wt.z * t2.z + wt.w * t3.z;
                v.w = wt.x * t0.w + wt.y * t1.w + wt.z * t2.w + wt.w * t3.w;
                uint32_t h01 = pack_bf16(v.x, v.y);
                uint32_t h23 = pack_bf16(v.z, v.w);
                __nv_bfloat162 hh01 = *(__nv_bfloat162*)&h01;
                __nv_bfloat162 hh23 = *(__nv_bfloat162*)&h23;
                float lx = v.x - __bfloat162float(hh01.x);
                float ly = v.y - __bfloat162float(hh01.y);
                float lz = v.z - __bfloat162float(hh23.x);
                float lw = v.w - __bfloat162float(hh23.y);
                int word = pp * BROW + gl8 * 2;
                *(uint2*)&sB[nbuf][0][word] = make_uint2(h01, h23);
                *(uint2*)&sB[nbuf][1][word] =
                    make_uint2(pack_bf16(lx, ly), pack_bf16(lz, lw));
            }
            __syncthreads();   // chunk nq ready
        }
        __syncthreads();       // match consumers' final barrier count
    } else {
        // ================= mma warps =================
        int wm = wid >> 1, wn = wid & 1;

        float acc[4][4][4];
        #pragma unroll
        for (int i = 0; i < 4; i++)
            #pragma unroll
            for (int j = 0; j < 4; j++)
                #pragma unroll
                for (int r = 0; r < 4; r++) acc[i][j][r] = 0.f;

        // B ldmatrix lane address (within a term plane)
        int mat = lane >> 3, mrow = lane & 7;
        int jd  = mat >> 1, kh = mat & 1;
        uint32_t lmB = ((wn * 32 + jd * 8 + mrow) * BROW + kh * 4) * 4;

        for (int q = 0; q < NCHUNK; q++) {
            __syncthreads();   // wait for chunk q
            int buf = q & 1;
            uint32_t bH = (uint32_t)__cvta_generic_to_shared(&sB[buf][0][0]);
            uint32_t bL = (uint32_t)__cvta_generic_to_shared(&sB[buf][1][0]);

            #pragma unroll
            for (int s = 0; s < 2; s++) {
                uint32_t soff = (uint32_t)(s * 32);
                uint32_t Bh[8], Bl[8];
                ldsm4(Bh + 0, bH + lmB + soff);
                ldsm4(Bh + 4, bH + lmB + soff + (uint32_t)(16 * BROW * 4));
                ldsm4(Bl + 0, bL + lmB + soff);
                ldsm4(Bl + 4, bL + lmB + soff + (uint32_t)(16 * BROW * 4));
                // A fragments straight from global (fragment-packed)
                uint4 Ah[4];
                #pragma unroll
                for (int i = 0; i < 4; i++)
                    Ah[i] = __ldg(&g_wA[(((q * 2 + 0) * 16 + wm * 4 + i) * 2 + s) * 32 + lane]);
                #pragma unroll
                for (int i = 0; i < 4; i++)
                    #pragma unroll
                    for (int j = 0; j < 4; j++)
                        mma16816(acc[i][j], (const uint32_t*)&Ah[i], Bh + 2 * j);
                #pragma unroll
                for (int i = 0; i < 4; i++)
                    #pragma unroll
                    for (int j = 0; j < 4; j++)
                        mma16816(acc[i][j], (const uint32_t*)&Ah[i], Bl + 2 * j);
                #pragma unroll
                for (int i = 0; i < 4; i++) {
                    uint4 Al = __ldg(&g_wA[(((q * 2 + 1) * 16 + wm * 4 + i) * 2 + s) * 32 + lane]);
                    #pragma unroll
                    for (int j = 0; j < 4; j++)
                        mma16816(acc[i][j], (const uint32_t*)&Al, Bh + 2 * j);
                }
            }
        }
        __syncthreads();       // final barrier (producers exit)

        // ---- epilogue: bias + NCHW store ----
        int q_ = lane >> 2, t = lane & 3;
        #pragma unroll
        for (int i = 0; i < 4; i++) {
            int o0 = wm * 64 + i * 16 + q_;
            float bias0 = __ldg(cb + o0);
            float bias1 = __ldg(cb + o0 + 8);
            float* r0 = out + (size_t)(b * COUT + o0) * HW + hw0 + wn * 32;
            float* r1 = out + (size_t)(b * COUT + o0 + 8) * HW + hw0 + wn * 32;
            #pragma unroll
            for (int j = 0; j < 4; j++) {
                float2 s0, s1;
                s0.x = acc[i][j][0] + bias0; s0.y = acc[i][j][1] + bias0;
                s1.x = acc[i][j][2] + bias1; s1.y = acc[i][j][3] + bias1;
                *(float2*)(r0 + j * 8 + t * 2) = s0;
                *(float2*)(r1 + j * 8 + t * 2) = s1;
            }
        }
    }
}

// ---------------- launch -----------------------------------------------------
extern "C" void kernel_launch(void* const* d_in, const int* in_sizes, int n_in,
                              void* d_out, int out_size) {
    const float* x  = (const float*)d_in[0];
    const float* ow = (const float*)d_in[1];
    const float* ob = (const float*)d_in[2];
    const float* cw = (const float*)d_in[3];
    const float* cb = (const float*)d_in[4];
    float* out      = (float*)d_out;

    {
        dim3 grid(HW / 32, C_ / 32, B_);
        dim3 block(32, 8);
        k_transpose<<<grid, block>>>(x);
    }
    k_prep<<<OWT_BLOCKS + (NCHUNK * 2 * 16 * 2 * 32) / 256, 256>>>(ow, cw);
    k_offset<<<B_ * HW / 32, 256>>>(x, ob);

    // one CTA per (batch, 64-pixel tile): 400 CTAs
    k_main<<<B_ * (HW / 64), 384>>>(cb, out);
}